// round 8
// baseline (speedup 1.0000x reference)
#include <cuda_runtime.h>
#include <cuda_fp16.h>

// InterpolateSparse2d on GB300 — round 7: split-grid producer/consumer.
// R5/R6 phase-barrier fusion stuck at ~136us: right byte count (423MB) but
// 3TB/s effective — block-serial items + phase barriers starved the memory
// system. v4: no phases, no ring. 592 persistent blocks stream the transpose
// (batch order); 296 blocks run the gather trailing by ~1-2 batches, gated by
// 16 per-batch counters (one poll per batch transition). Scratch is full-size
// write-once (no WAR, no aliasing); gather reads it from L2 while hot.

#define BB 16
#define CC 64
#define HX 240
#define WX 320
#define NN 20000
#define HW (HX * WX)

#define CH_T 2400                    // transpose chunks per batch (32 px each)
#define CH_G 625                     // gather chunks per batch (32 pts each)

#define T_BLOCKS 592
#define G_BLOCKS 296
#define GRID_BLOCKS (T_BLOCKS + G_BLOCKS)   // 888 = 148 SM * 6, all resident

// Full scratch [B][H][W][64ch fp16] = 157MB, written once per launch.
__device__ uint4 g_scr[(long long)BB * HW * 8];
__device__ int g_tdone[BB];          // transpose chunks completed per batch

__global__ void init_counters()
{
    int t = threadIdx.x;
    if (t < BB) g_tdone[t] = 0;
}

__global__ void __launch_bounds__(256, 6)
fused_interp4(const float* __restrict__ x,
              const float* __restrict__ pos,
              const int* __restrict__ Hp,
              const int* __restrict__ Wp,
              float* __restrict__ out)
{
    const int tid = threadIdx.x;

    if (blockIdx.x < T_BLOCKS) {
        // ================= producer: transpose NCHW fp32 -> NHWC fp16 =======
        __shared__ float tile[64 * 33];

        for (int ch = blockIdx.x; ch < BB * CH_T; ch += T_BLOCKS) {
            int b  = ch / CH_T;
            int p0 = (ch - b * CH_T) * 32;

            int pl = tid & 31;             // pixel lane
            int c0 = tid >> 5;             // 0..7

            const float* src = x + (long long)b * CC * HW + p0;
            #pragma unroll
            for (int i = 0; i < 8; i++) {
                int c = c0 + i * 8;
                // evict-first: x is single-use; don't evict hot scratch.
                tile[c * 33 + pl] = __ldcs(src + (long long)c * HW + pl);
            }
            __syncthreads();

            int c2 = tid & 31;             // half2 index (channels 2c2,2c2+1)
            int pg = tid >> 5;             // 0..7
            __half2* dst = (__half2*)(g_scr + ((long long)b * HW + p0) * 8);
            #pragma unroll
            for (int i = 0; i < 4; i++) {
                int p = pg + i * 8;
                float lo = tile[(2 * c2)     * 33 + p];
                float hi = tile[(2 * c2 + 1) * 33 + p];
                dst[p * 32 + c2] = __floats2half2_rn(lo, hi);
            }

            __threadfence();               // make this thread's stores visible
            __syncthreads();               // all threads' stores fenced; tile safe
            if (tid == 0) atomicAdd(&g_tdone[b], 1);   // publish chunk
        }
    } else {
        // ================= consumer: bilinear gather from fp16 NHWC =========
        const float Wf = (float)(*Wp);
        const float Hf = (float)(*Hp);
        __shared__ int s_ready;            // highest batch known complete + 1

        if (tid == 0) s_ready = 0;
        __syncthreads();

        int gid = blockIdx.x - T_BLOCKS;
        for (int g = gid; g < BB * CH_G; g += G_BLOCKS) {
            int b = g / CH_G;

            // Wait (once per batch transition) until batch b fully transposed.
            if (s_ready <= b) {
                if (tid == 0) {
                    while (atomicAdd(&g_tdone[b], 0) < CH_T) __nanosleep(128);
                    __threadfence();       // acquire scratch writes
                    s_ready = b + 1;
                }
                __syncthreads();
            }

            int chunk = g - b * CH_G;
            int lane8 = tid & 7;           // 8 channels per lane
            int p     = chunk * 32 + (tid >> 3);
            long long pn = (long long)b * NN + p;

            float posx = pos[pn * 2 + 0];
            float posy = pos[pn * 2 + 1];

            float px = posx * (float)(WX - 1) / Wf;
            float py = posy * (float)(HX - 1) / Hf;

            int x0 = (int)floorf(px);
            int y0 = (int)floorf(py);
            x0 = min(max(x0, 0), WX - 1);
            y0 = min(max(y0, 0), HX - 1);
            int x1 = min(x0 + 1, WX - 1);
            int y1 = min(y0 + 1, HX - 1);

            float x0f = (float)x0, x1f = (float)x1;
            float y0f = (float)y0, y1f = (float)y1;

            float wa = (x1f - px) * (y1f - py);
            float wb = (x1f - px) * (py - y0f);
            float wc = (px - x0f) * (y1f - py);
            float wd = (px - x0f) * (py - y0f);

            long long bufb = (long long)b * HW;
            long long i00 = (bufb + y0 * WX + x0) * 8 + lane8;
            long long i01 = (bufb + y0 * WX + x1) * 8 + lane8;
            long long i10 = (bufb + y1 * WX + x0) * 8 + lane8;
            long long i11 = (bufb + y1 * WX + x1) * 8 + lane8;

            uint4 A  = __ldg(g_scr + i00);
            uint4 Bv = __ldg(g_scr + i10);
            uint4 Cv = __ldg(g_scr + i01);
            uint4 D  = __ldg(g_scr + i11);

            float r[8];
            const unsigned* au = (const unsigned*)&A;
            const unsigned* bu = (const unsigned*)&Bv;
            const unsigned* cu = (const unsigned*)&Cv;
            const unsigned* du = (const unsigned*)&D;
            #pragma unroll
            for (int j = 0; j < 4; j++) {
                float2 fa = __half22float2(*(const __half2*)&au[j]);
                float2 fb = __half22float2(*(const __half2*)&bu[j]);
                float2 fc = __half22float2(*(const __half2*)&cu[j]);
                float2 fd = __half22float2(*(const __half2*)&du[j]);
                r[2 * j + 0] = wa * fa.x + wb * fb.x + wc * fc.x + wd * fd.x;
                r[2 * j + 1] = wa * fa.y + wb * fb.y + wc * fc.y + wd * fd.y;
            }

            // evict-first store: out is write-once.
            float4* o = (float4*)out;
            long long ob = pn * 16 + lane8 * 2;
            __stcs(o + ob + 0, make_float4(r[0], r[1], r[2], r[3]));
            __stcs(o + ob + 1, make_float4(r[4], r[5], r[6], r[7]));
        }
    }
}

extern "C" void kernel_launch(void* const* d_in, const int* in_sizes, int n_in,
                              void* d_out, int out_size)
{
    const float* x   = (const float*)d_in[0];
    const float* pos = (const float*)d_in[1];
    const int*   Hp  = (const int*)d_in[2];
    const int*   Wp  = (const int*)d_in[3];
    float* out = (float*)d_out;

    init_counters<<<1, 32>>>();
    fused_interp4<<<GRID_BLOCKS, 256>>>(x, pos, Hp, Wp, out);
}